// round 1
// baseline (speedup 1.0000x reference)
#include <cuda_runtime.h>
#include <math.h>
#include <stdint.h>

// Problem constants (CrossAttention_7756710936941)
#define B_BATCH 2
#define LQ      2048
#define LK      2048
#define DIM     1024
#define DCTX    768
#define NH      16
#define HD      64
#define MROWS   (B_BATCH * LQ)   // 4096 flattened rows for q / context

// Scratch (allocation-free: device globals)
__device__ float g_q[(size_t)MROWS * DIM];
__device__ float g_k[(size_t)MROWS * DIM];
__device__ float g_v[(size_t)MROWS * DIM];
__device__ float g_att[(size_t)MROWS * DIM];

// ---------------------------------------------------------------------------
// GEMM with bias: C[M,N] = A[M,K] @ Bw[K,N] + bias[N]
// 128x128 block tile, K-tile 8, 256 threads, 8x8 per-thread microtile.
// M,N multiples of 128; K multiple of 8 (holds for 1024/768).
// ---------------------------------------------------------------------------
__global__ __launch_bounds__(256) void gemm_bias_kernel(
    const float* __restrict__ A, const float* __restrict__ Bw,
    const float* __restrict__ bias, float* __restrict__ C,
    int M, int N, int K)
{
    __shared__ float As[8][128];   // transposed: As[k][m]
    __shared__ float Bs[8][128];   // Bs[k][n]

    const int t  = threadIdx.x;
    const int ty = t >> 4;         // 0..15
    const int tx = t & 15;         // 0..15
    const int m0 = blockIdx.y * 128;
    const int n0 = blockIdx.x * 128;

    float acc[8][8];
#pragma unroll
    for (int i = 0; i < 8; i++)
#pragma unroll
        for (int j = 0; j < 8; j++) acc[i][j] = 0.0f;

    const int ar = t >> 1;            // 0..127
    const int ak = (t & 1) * 4;       // 0 or 4
    const int br = t >> 5;            // 0..7
    const int bc = (t & 31) * 4;      // 0..124

    for (int k0 = 0; k0 < K; k0 += 8) {
        // stage loads in registers (overlaps with previous tile's compute)
        float4 av = *(const float4*)(A  + (size_t)(m0 + ar) * K + k0 + ak);
        float4 bv = *(const float4*)(Bw + (size_t)(k0 + br) * N + n0 + bc);
        __syncthreads();
        As[ak + 0][ar] = av.x;
        As[ak + 1][ar] = av.y;
        As[ak + 2][ar] = av.z;
        As[ak + 3][ar] = av.w;
        *(float4*)&Bs[br][bc] = bv;
        __syncthreads();

#pragma unroll
        for (int kk = 0; kk < 8; kk++) {
            float4 a0 = *(const float4*)&As[kk][ty * 8];
            float4 a1 = *(const float4*)&As[kk][ty * 8 + 4];
            float4 b0 = *(const float4*)&Bs[kk][tx * 8];
            float4 b1 = *(const float4*)&Bs[kk][tx * 8 + 4];
            float a[8] = {a0.x, a0.y, a0.z, a0.w, a1.x, a1.y, a1.z, a1.w};
            float b[8] = {b0.x, b0.y, b0.z, b0.w, b1.x, b1.y, b1.z, b1.w};
#pragma unroll
            for (int i = 0; i < 8; i++)
#pragma unroll
                for (int j = 0; j < 8; j++)
                    acc[i][j] = fmaf(a[i], b[j], acc[i][j]);
        }
    }

    // epilogue: add bias, store
#pragma unroll
    for (int i = 0; i < 8; i++) {
        const int m = m0 + ty * 8 + i;
        float* crow = C + (size_t)m * N + n0 + tx * 8;
#pragma unroll
        for (int j = 0; j < 8; j += 4) {
            float4 o;
            o.x = acc[i][j + 0] + bias[n0 + tx * 8 + j + 0];
            o.y = acc[i][j + 1] + bias[n0 + tx * 8 + j + 1];
            o.z = acc[i][j + 2] + bias[n0 + tx * 8 + j + 2];
            o.w = acc[i][j + 3] + bias[n0 + tx * 8 + j + 3];
            *(float4*)(crow + j) = o;
        }
    }
}

// ---------------------------------------------------------------------------
// Flash cross-attention, one (batch, head, 64-row q tile) per CTA.
// Br=64 q rows, Bc=32 keys per inner tile, head dim 64, online softmax.
// 256 threads as 16x16: thread (ty,tx) owns S rows ty*4..+3 x cols tx*2..+1,
// and O rows ty*4..+3 x dims tx*4..+3.
// ---------------------------------------------------------------------------
__global__ __launch_bounds__(256) void attn_kernel(
    const float* __restrict__ gq, const float* __restrict__ gk,
    const float* __restrict__ gv, float* __restrict__ gatt)
{
    __shared__ float Qs[64][68];   // stride 68: float4-aligned, pad vs bank conflicts
    __shared__ float Ks[32][68];
    __shared__ float Vs[32][68];
    __shared__ float Ps[64][36];

    const int bh = blockIdx.x;           // 0..31
    const int b  = bh >> 4;
    const int h  = bh & 15;
    const int qt = blockIdx.y;           // 0..31 (64-row q tiles)

    const int t  = threadIdx.x;
    const int ty = t >> 4;               // 0..15
    const int tx = t & 15;               // 0..15
    const int ty4 = ty * 4;
    const int tx2 = tx * 2;
    const int tx4 = tx * 4;

    const float* qbase = gq + (size_t)b * LQ * DIM + (size_t)h * HD;
    const float* kbase = gk + (size_t)b * LK * DIM + (size_t)h * HD;
    const float* vbase = gv + (size_t)b * LK * DIM + (size_t)h * HD;

    // load Q tile: 64 rows x 64 dims, float4 (4 per thread)
    for (int it = t; it < 64 * 16; it += 256) {
        int r = it >> 4, d = (it & 15) * 4;
        *(float4*)&Qs[r][d] =
            *(const float4*)(qbase + (size_t)(qt * 64 + r) * DIM + d);
    }

    float m_i[4], l_i[4], O[4][4];
#pragma unroll
    for (int i = 0; i < 4; i++) {
        m_i[i] = -1e30f;
        l_i[i] = 0.0f;
#pragma unroll
        for (int j = 0; j < 4; j++) O[i][j] = 0.0f;
    }

    const float scale = 0.125f;          // 1/sqrt(64)

    for (int kt = 0; kt < LK / 32; kt++) {
        __syncthreads();   // previous iteration done reading Ks/Vs/Ps
        // load K,V tiles: 32x64 each, float4 (2+2 per thread)
        for (int it = t; it < 32 * 16; it += 256) {
            int r = it >> 4, d = (it & 15) * 4;
            *(float4*)&Ks[r][d] =
                *(const float4*)(kbase + (size_t)(kt * 32 + r) * DIM + d);
            *(float4*)&Vs[r][d] =
                *(const float4*)(vbase + (size_t)(kt * 32 + r) * DIM + d);
        }
        __syncthreads();

        // S = scale * Q K^T   (4 rows x 2 cols per thread)
        float s[4][2] = {{0, 0}, {0, 0}, {0, 0}, {0, 0}};
#pragma unroll 2
        for (int d = 0; d < 64; d += 4) {
            float4 k0 = *(const float4*)&Ks[tx2 + 0][d];
            float4 k1 = *(const float4*)&Ks[tx2 + 1][d];
#pragma unroll
            for (int i = 0; i < 4; i++) {
                float4 q = *(const float4*)&Qs[ty4 + i][d];
                s[i][0] = fmaf(q.x, k0.x, fmaf(q.y, k0.y,
                          fmaf(q.z, k0.z, fmaf(q.w, k0.w, s[i][0]))));
                s[i][1] = fmaf(q.x, k1.x, fmaf(q.y, k1.y,
                          fmaf(q.z, k1.z, fmaf(q.w, k1.w, s[i][1]))));
            }
        }
#pragma unroll
        for (int i = 0; i < 4; i++) { s[i][0] *= scale; s[i][1] *= scale; }

        // row max across the 16 tx lanes
        float mt[4];
#pragma unroll
        for (int i = 0; i < 4; i++) mt[i] = fmaxf(s[i][0], s[i][1]);
#pragma unroll
        for (int off = 1; off < 16; off <<= 1)
#pragma unroll
            for (int i = 0; i < 4; i++)
                mt[i] = fmaxf(mt[i], __shfl_xor_sync(0xffffffffu, mt[i], off));

        float alpha[4], lsum[4];
#pragma unroll
        for (int i = 0; i < 4; i++) {
            float mnew = fmaxf(m_i[i], mt[i]);
            alpha[i] = __expf(m_i[i] - mnew);
            m_i[i] = mnew;
            float p0 = __expf(s[i][0] - mnew);
            float p1 = __expf(s[i][1] - mnew);
            Ps[ty4 + i][tx2 + 0] = p0;
            Ps[ty4 + i][tx2 + 1] = p1;
            lsum[i] = p0 + p1;
        }
#pragma unroll
        for (int off = 1; off < 16; off <<= 1)
#pragma unroll
            for (int i = 0; i < 4; i++)
                lsum[i] += __shfl_xor_sync(0xffffffffu, lsum[i], off);
#pragma unroll
        for (int i = 0; i < 4; i++) {
            l_i[i] = l_i[i] * alpha[i] + lsum[i];
#pragma unroll
            for (int j = 0; j < 4; j++) O[i][j] *= alpha[i];
        }
        __syncthreads();   // Ps fully written before PV reads

        // O += P @ V   (4 rows x 4 dims per thread)
#pragma unroll
        for (int c = 0; c < 32; c += 4) {
            float4 va = *(const float4*)&Vs[c + 0][tx4];
            float4 vb = *(const float4*)&Vs[c + 1][tx4];
            float4 vc = *(const float4*)&Vs[c + 2][tx4];
            float4 vd = *(const float4*)&Vs[c + 3][tx4];
#pragma unroll
            for (int i = 0; i < 4; i++) {
                float4 p = *(const float4*)&Ps[ty4 + i][c];
                O[i][0] = fmaf(p.x, va.x, fmaf(p.y, vb.x,
                          fmaf(p.z, vc.x, fmaf(p.w, vd.x, O[i][0]))));
                O[i][1] = fmaf(p.x, va.y, fmaf(p.y, vb.y,
                          fmaf(p.z, vc.y, fmaf(p.w, vd.y, O[i][1]))));
                O[i][2] = fmaf(p.x, va.z, fmaf(p.y, vb.z,
                          fmaf(p.z, vc.z, fmaf(p.w, vd.z, O[i][2]))));
                O[i][3] = fmaf(p.x, va.w, fmaf(p.y, vb.w,
                          fmaf(p.z, vc.w, fmaf(p.w, vd.w, O[i][3]))));
            }
        }
    }

    // finalize: divide by l, store
    float* obase = gatt + (size_t)(b * LQ + qt * 64) * DIM + (size_t)h * HD;
#pragma unroll
    for (int i = 0; i < 4; i++) {
        float inv = 1.0f / l_i[i];
        float4 o;
        o.x = O[i][0] * inv; o.y = O[i][1] * inv;
        o.z = O[i][2] * inv; o.w = O[i][3] * inv;
        *(float4*)(obase + (size_t)(ty4 + i) * DIM + tx4) = o;
    }
}

// ---------------------------------------------------------------------------
// Launch
// ---------------------------------------------------------------------------
extern "C" void kernel_launch(void* const* d_in, const int* in_sizes, int n_in,
                              void* d_out, int out_size)
{
    const float* x    = (const float*)d_in[0];
    const float* ctx  = (const float*)d_in[1];
    const float* w_q  = (const float*)d_in[2];
    const float* b_q  = (const float*)d_in[3];
    const float* w_k  = (const float*)d_in[4];
    const float* b_k  = (const float*)d_in[5];
    const float* w_v  = (const float*)d_in[6];
    const float* b_v  = (const float*)d_in[7];
    const float* w_o  = (const float*)d_in[8];
    const float* b_o  = (const float*)d_in[9];
    float* out = (float*)d_out;

    float *pq, *pk, *pv, *patt;
    cudaGetSymbolAddress((void**)&pq,   g_q);
    cudaGetSymbolAddress((void**)&pk,   g_k);
    cudaGetSymbolAddress((void**)&pv,   g_v);
    cudaGetSymbolAddress((void**)&patt, g_att);

    dim3 gb(DIM / 128, MROWS / 128);   // (8, 32)
    gemm_bias_kernel<<<gb, 256>>>(x,   w_q, b_q, pq, MROWS, DIM, DIM);
    gemm_bias_kernel<<<gb, 256>>>(ctx, w_k, b_k, pk, MROWS, DIM, DCTX);
    gemm_bias_kernel<<<gb, 256>>>(ctx, w_v, b_v, pv, MROWS, DIM, DCTX);

    dim3 ga(B_BATCH * NH, LQ / 64);    // (32, 32)
    attn_kernel<<<ga, 256>>>(pq, pk, pv, patt);

    gemm_bias_kernel<<<gb, 256>>>(patt, w_o, b_o, out, MROWS, DIM, DIM);
}

// round 2
// speedup vs baseline: 2.1168x; 2.1168x over previous
#include <cuda_runtime.h>
#include <stdint.h>
#include <math.h>

// Problem constants (CrossAttention_7756710936941)
#define B_BATCH 2
#define LQ      2048
#define LK      2048
#define DIM     1024
#define DCTX    768
#define NH      16
#define HD      64
#define MROWS   (B_BATCH * LQ)

// Scratch (allocation-free: device globals)
__device__ float g_q[(size_t)MROWS * DIM];
__device__ float g_k[(size_t)MROWS * DIM];
__device__ float g_v[(size_t)MROWS * DIM];
__device__ float g_att[(size_t)MROWS * DIM];

// ---------------------------------------------------------------------------
// tf32 helpers
// ---------------------------------------------------------------------------
__device__ __forceinline__ uint32_t f2tf(float x) {
    uint32_t u;
    asm("cvt.rna.tf32.f32 %0, %1;" : "=r"(u) : "f"(x));
    return u;
}
__device__ __forceinline__ float f2tf_f(float x) { return __uint_as_float(f2tf(x)); }

// D += A(16x8) * B(8x8), tf32 inputs, f32 accum.
// A frag: a0=(g,tg) a1=(g+8,tg) a2=(g,tg+4) a3=(g+8,tg+4)   [row,colK]
// B frag: b0=(k=tg, n=g) b1=(k=tg+4, n=g)
// C frag: c0=(g,2tg) c1=(g,2tg+1) c2=(g+8,2tg) c3=(g+8,2tg+1)
__device__ __forceinline__ void mma_tf32(float c[4],
    uint32_t a0, uint32_t a1, uint32_t a2, uint32_t a3,
    uint32_t b0, uint32_t b1)
{
    asm volatile(
        "mma.sync.aligned.m16n8k8.row.col.f32.tf32.tf32.f32 "
        "{%0,%1,%2,%3},{%4,%5,%6,%7},{%8,%9},{%0,%1,%2,%3};"
        : "+f"(c[0]), "+f"(c[1]), "+f"(c[2]), "+f"(c[3])
        : "r"(a0), "r"(a1), "r"(a2), "r"(a3), "r"(b0), "r"(b1));
}

// ---------------------------------------------------------------------------
// 3xTF32 GEMM with bias: C[M,N] = A[M,K] @ Bw[K,N] + bias[N]  (~fp32 accuracy)
// 128x128 block, BK=16, 256 threads = 8 warps (4 m-warps x 2 n-warps),
// warp tile 32x64 = 2 m16-tiles x 8 n8-tiles.
// Smem row stride 136 words => fragment loads (8*tg+g banks) conflict-free.
// ---------------------------------------------------------------------------
#define GS 136

__global__ __launch_bounds__(256, 2) void gemm3x(
    const float* __restrict__ A, const float* __restrict__ Bw,
    const float* __restrict__ bias, float* __restrict__ C,
    int M, int N, int K)
{
    __shared__ float Ah[16][GS], Al[16][GS], Bh[16][GS], Bl[16][GS];

    const int t    = threadIdx.x;
    const int lane = t & 31;
    const int w    = t >> 5;
    const int g    = lane >> 2, tg = lane & 3;
    const int wm   = w >> 1,    wn = w & 1;
    const int m0   = blockIdx.y * 128, n0 = blockIdx.x * 128;

    float c[2][8][4];
#pragma unroll
    for (int i = 0; i < 2; i++)
#pragma unroll
        for (int j = 0; j < 8; j++)
#pragma unroll
            for (int e = 0; e < 4; e++) c[i][j][e] = 0.0f;

    const int ar0 = t >> 2,  ak0 = (t & 3) * 4;    // A: rows ar0, ar0+64
    const int br0 = t >> 5,  bn0 = (t & 31) * 4;   // B: k-rows br0, br0+8

    float4 ra0 = *(const float4*)(A + (size_t)(m0 + ar0) * K + ak0);
    float4 ra1 = *(const float4*)(A + (size_t)(m0 + ar0 + 64) * K + ak0);
    float4 rb0 = *(const float4*)(Bw + (size_t)br0 * N + n0 + bn0);
    float4 rb1 = *(const float4*)(Bw + (size_t)(br0 + 8) * N + n0 + bn0);

    for (int k0 = 0; k0 < K; k0 += 16) {
        __syncthreads();
        {
            float va[4] = {ra0.x, ra0.y, ra0.z, ra0.w};
#pragma unroll
            for (int e = 0; e < 4; e++) {
                float hi = f2tf_f(va[e]);
                Ah[ak0 + e][ar0] = hi;
                Al[ak0 + e][ar0] = f2tf_f(va[e] - hi);
            }
            float vb[4] = {ra1.x, ra1.y, ra1.z, ra1.w};
#pragma unroll
            for (int e = 0; e < 4; e++) {
                float hi = f2tf_f(vb[e]);
                Ah[ak0 + e][ar0 + 64] = hi;
                Al[ak0 + e][ar0 + 64] = f2tf_f(vb[e] - hi);
            }
            float4 h0, l0, h1, l1;
            h0.x = f2tf_f(rb0.x); l0.x = f2tf_f(rb0.x - h0.x);
            h0.y = f2tf_f(rb0.y); l0.y = f2tf_f(rb0.y - h0.y);
            h0.z = f2tf_f(rb0.z); l0.z = f2tf_f(rb0.z - h0.z);
            h0.w = f2tf_f(rb0.w); l0.w = f2tf_f(rb0.w - h0.w);
            h1.x = f2tf_f(rb1.x); l1.x = f2tf_f(rb1.x - h1.x);
            h1.y = f2tf_f(rb1.y); l1.y = f2tf_f(rb1.y - h1.y);
            h1.z = f2tf_f(rb1.z); l1.z = f2tf_f(rb1.z - h1.z);
            h1.w = f2tf_f(rb1.w); l1.w = f2tf_f(rb1.w - h1.w);
            *(float4*)&Bh[br0][bn0]     = h0;
            *(float4*)&Bl[br0][bn0]     = l0;
            *(float4*)&Bh[br0 + 8][bn0] = h1;
            *(float4*)&Bl[br0 + 8][bn0] = l1;
        }
        __syncthreads();

        if (k0 + 16 < K) {   // prefetch next tile while computing
            ra0 = *(const float4*)(A + (size_t)(m0 + ar0) * K + k0 + 16 + ak0);
            ra1 = *(const float4*)(A + (size_t)(m0 + ar0 + 64) * K + k0 + 16 + ak0);
            rb0 = *(const float4*)(Bw + (size_t)(k0 + 16 + br0) * N + n0 + bn0);
            rb1 = *(const float4*)(Bw + (size_t)(k0 + 24 + br0) * N + n0 + bn0);
        }

#pragma unroll
        for (int ks = 0; ks < 16; ks += 8) {
            uint32_t ah[2][4], alr[2][4];
#pragma unroll
            for (int mt = 0; mt < 2; mt++) {
                const int r = wm * 32 + mt * 16;
                ah[mt][0]  = __float_as_uint(Ah[ks + tg][r + g]);
                ah[mt][1]  = __float_as_uint(Ah[ks + tg][r + g + 8]);
                ah[mt][2]  = __float_as_uint(Ah[ks + tg + 4][r + g]);
                ah[mt][3]  = __float_as_uint(Ah[ks + tg + 4][r + g + 8]);
                alr[mt][0] = __float_as_uint(Al[ks + tg][r + g]);
                alr[mt][1] = __float_as_uint(Al[ks + tg][r + g + 8]);
                alr[mt][2] = __float_as_uint(Al[ks + tg + 4][r + g]);
                alr[mt][3] = __float_as_uint(Al[ks + tg + 4][r + g + 8]);
            }
#pragma unroll
            for (int nt = 0; nt < 8; nt++) {
                const int cb = wn * 64 + nt * 8 + g;
                uint32_t bh0 = __float_as_uint(Bh[ks + tg][cb]);
                uint32_t bh1 = __float_as_uint(Bh[ks + tg + 4][cb]);
                uint32_t bl0 = __float_as_uint(Bl[ks + tg][cb]);
                uint32_t bl1 = __float_as_uint(Bl[ks + tg + 4][cb]);
#pragma unroll
                for (int mt = 0; mt < 2; mt++) {
                    mma_tf32(c[mt][nt], ah[mt][0], ah[mt][1], ah[mt][2], ah[mt][3], bh0, bh1);
                    mma_tf32(c[mt][nt], ah[mt][0], ah[mt][1], ah[mt][2], ah[mt][3], bl0, bl1);
                    mma_tf32(c[mt][nt], alr[mt][0], alr[mt][1], alr[mt][2], alr[mt][3], bh0, bh1);
                }
            }
        }
    }

    // epilogue: bias + store (float2 per row-half)
#pragma unroll
    for (int mt = 0; mt < 2; mt++) {
        const int r = m0 + wm * 32 + mt * 16 + g;
#pragma unroll
        for (int nt = 0; nt < 8; nt++) {
            const int col = n0 + wn * 64 + nt * 8 + 2 * tg;
            const float b0v = bias[col], b1v = bias[col + 1];
            float2 s0 = make_float2(c[mt][nt][0] + b0v, c[mt][nt][1] + b1v);
            float2 s1 = make_float2(c[mt][nt][2] + b0v, c[mt][nt][3] + b1v);
            *(float2*)(C + (size_t)r * N + col)       = s0;
            *(float2*)(C + (size_t)(r + 8) * N + col) = s1;
        }
    }
}

// ---------------------------------------------------------------------------
// Flash cross-attention on tf32 tensor MMA.
// CTA = (b, h, 128-row q-tile), 8 warps; warp owns 16 q-rows (full softmax
// locality: no cross-warp reductions). Bc = 64 keys per step, HD = 64.
// S and PV via m16n8k8.tf32; online softmax in fp32; P round-trips through
// smem (tf32) — each warp reads back only its own rows => __syncwarp only.
// Smem strides 68/72 make every fragment load bank-conflict-free.
// ---------------------------------------------------------------------------
#define QSTR 68
#define VSTR 72
#define ATTN_SMEM_FLOATS (128 * QSTR + 64 * QSTR + 64 * VSTR + 128 * QSTR)

__global__ __launch_bounds__(256, 2) void attn_mma(
    const float* __restrict__ gq, const float* __restrict__ gk,
    const float* __restrict__ gv, float* __restrict__ gatt)
{
    extern __shared__ float smbuf[];
    float* Qs = smbuf;                    // [128][68]
    float* Ks = Qs + 128 * QSTR;          // [64][68]
    float* Vs = Ks + 64 * QSTR;           // [64][72]
    float* Ps = Vs + 64 * VSTR;           // [128][68]

    const int t    = threadIdx.x;
    const int lane = t & 31;
    const int w    = t >> 5;
    const int g    = lane >> 2, tg = lane & 3;
    const int m0   = w * 16;
    const int bh   = blockIdx.x;
    const int b    = bh >> 4, h = bh & 15;
    const int qt   = blockIdx.y;

    const float* qb  = gq + ((size_t)b * LQ + qt * 128) * DIM + h * HD;
    const float* kbp = gk + (size_t)b * LK * DIM + h * HD;
    const float* vbp = gv + (size_t)b * LK * DIM + h * HD;

    // Q tile: scale by 1/sqrt(HD), convert to tf32 once
#pragma unroll
    for (int j = 0; j < 8; j++) {
        int it = t + 256 * j;
        int r = it >> 4, d = (it & 15) * 4;
        float4 v = *(const float4*)(qb + (size_t)r * DIM + d);
        float4 o;
        o.x = f2tf_f(v.x * 0.125f); o.y = f2tf_f(v.y * 0.125f);
        o.z = f2tf_f(v.z * 0.125f); o.w = f2tf_f(v.w * 0.125f);
        *(float4*)&Qs[r * QSTR + d] = o;
    }

    float oacc[8][4];
#pragma unroll
    for (int dt = 0; dt < 8; dt++)
#pragma unroll
        for (int e = 0; e < 4; e++) oacc[dt][e] = 0.0f;
    float mrow0 = -1e30f, mrow1 = -1e30f, lrow0 = 0.0f, lrow1 = 0.0f;

    for (int kt = 0; kt < LK / 64; kt++) {
        __syncthreads();   // previous S/PV done with Ks/Vs
#pragma unroll
        for (int j = 0; j < 4; j++) {
            int it = t + 256 * j;
            int r = it >> 4, d = (it & 15) * 4;
            float4 kv = *(const float4*)(kbp + (size_t)(kt * 64 + r) * DIM + d);
            float4 vv = *(const float4*)(vbp + (size_t)(kt * 64 + r) * DIM + d);
            float4 ko, vo;
            ko.x = f2tf_f(kv.x); ko.y = f2tf_f(kv.y);
            ko.z = f2tf_f(kv.z); ko.w = f2tf_f(kv.w);
            vo.x = f2tf_f(vv.x); vo.y = f2tf_f(vv.y);
            vo.z = f2tf_f(vv.z); vo.w = f2tf_f(vv.w);
            *(float4*)&Ks[r * QSTR + d] = ko;
            *(float4*)&Vs[r * VSTR + d] = vo;
        }
        __syncthreads();

        // S = Q K^T  (warp: 16 x 64)
        float sc[8][4];
#pragma unroll
        for (int nt = 0; nt < 8; nt++)
#pragma unroll
            for (int e = 0; e < 4; e++) sc[nt][e] = 0.0f;

#pragma unroll
        for (int k0 = 0; k0 < 64; k0 += 8) {
            uint32_t a0 = __float_as_uint(Qs[(m0 + g) * QSTR + k0 + tg]);
            uint32_t a1 = __float_as_uint(Qs[(m0 + g + 8) * QSTR + k0 + tg]);
            uint32_t a2 = __float_as_uint(Qs[(m0 + g) * QSTR + k0 + tg + 4]);
            uint32_t a3 = __float_as_uint(Qs[(m0 + g + 8) * QSTR + k0 + tg + 4]);
#pragma unroll
            for (int nt = 0; nt < 8; nt++) {
                uint32_t b0 = __float_as_uint(Ks[(nt * 8 + g) * QSTR + k0 + tg]);
                uint32_t b1 = __float_as_uint(Ks[(nt * 8 + g) * QSTR + k0 + tg + 4]);
                mma_tf32(sc[nt], a0, a1, a2, a3, b0, b1);
            }
        }

        // online softmax (rows g and g+8; reduce across the tg quad)
        float mt0 = -1e30f, mt1 = -1e30f;
#pragma unroll
        for (int nt = 0; nt < 8; nt++) {
            mt0 = fmaxf(mt0, fmaxf(sc[nt][0], sc[nt][1]));
            mt1 = fmaxf(mt1, fmaxf(sc[nt][2], sc[nt][3]));
        }
        mt0 = fmaxf(mt0, __shfl_xor_sync(0xffffffffu, mt0, 1));
        mt0 = fmaxf(mt0, __shfl_xor_sync(0xffffffffu, mt0, 2));
        mt1 = fmaxf(mt1, __shfl_xor_sync(0xffffffffu, mt1, 1));
        mt1 = fmaxf(mt1, __shfl_xor_sync(0xffffffffu, mt1, 2));

        float mn0 = fmaxf(mrow0, mt0), mn1 = fmaxf(mrow1, mt1);
        float al0 = __expf(mrow0 - mn0), al1 = __expf(mrow1 - mn1);
        mrow0 = mn0; mrow1 = mn1;

        float ls0 = 0.0f, ls1 = 0.0f;
#pragma unroll
        for (int nt = 0; nt < 8; nt++) {
            float p0 = __expf(sc[nt][0] - mn0);
            float p1 = __expf(sc[nt][1] - mn0);
            float p2 = __expf(sc[nt][2] - mn1);
            float p3 = __expf(sc[nt][3] - mn1);
            ls0 += p0 + p1; ls1 += p2 + p3;
            float2 w0 = make_float2(f2tf_f(p0), f2tf_f(p1));
            float2 w1 = make_float2(f2tf_f(p2), f2tf_f(p3));
            *(float2*)&Ps[(m0 + g) * QSTR + nt * 8 + 2 * tg]     = w0;
            *(float2*)&Ps[(m0 + g + 8) * QSTR + nt * 8 + 2 * tg] = w1;
        }
        ls0 += __shfl_xor_sync(0xffffffffu, ls0, 1);
        ls0 += __shfl_xor_sync(0xffffffffu, ls0, 2);
        ls1 += __shfl_xor_sync(0xffffffffu, ls1, 1);
        ls1 += __shfl_xor_sync(0xffffffffu, ls1, 2);
        lrow0 = lrow0 * al0 + ls0;
        lrow1 = lrow1 * al1 + ls1;
#pragma unroll
        for (int dt = 0; dt < 8; dt++) {
            oacc[dt][0] *= al0; oacc[dt][1] *= al0;
            oacc[dt][2] *= al1; oacc[dt][3] *= al1;
        }
        __syncwarp();   // P stores visible warp-wide (warp reads only its own rows)

        // O += P V  (warp: 16 x 64)
#pragma unroll
        for (int kk = 0; kk < 64; kk += 8) {
            uint32_t a0 = __float_as_uint(Ps[(m0 + g) * QSTR + kk + tg]);
            uint32_t a1 = __float_as_uint(Ps[(m0 + g + 8) * QSTR + kk + tg]);
            uint32_t a2 = __float_as_uint(Ps[(m0 + g) * QSTR + kk + tg + 4]);
            uint32_t a3 = __float_as_uint(Ps[(m0 + g + 8) * QSTR + kk + tg + 4]);
#pragma unroll
            for (int dt = 0; dt < 8; dt++) {
                uint32_t b0 = __float_as_uint(Vs[(kk + tg) * VSTR + dt * 8 + g]);
                uint32_t b1 = __float_as_uint(Vs[(kk + tg + 4) * VSTR + dt * 8 + g]);
                mma_tf32(oacc[dt], a0, a1, a2, a3, b0, b1);
            }
        }
    }

    const float i0 = 1.0f / lrow0, i1 = 1.0f / lrow1;
    float* ob = gatt + ((size_t)b * LQ + qt * 128) * DIM + h * HD;
#pragma unroll
    for (int dt = 0; dt < 8; dt++) {
        const int col = dt * 8 + 2 * tg;
        float2 s0 = make_float2(oacc[dt][0] * i0, oacc[dt][1] * i0);
        float2 s1 = make_float2(oacc[dt][2] * i1, oacc[dt][3] * i1);
        *(float2*)(ob + (size_t)(m0 + g) * DIM + col)     = s0;
        *(float2*)(ob + (size_t)(m0 + g + 8) * DIM + col) = s1;
    }
}

// ---------------------------------------------------------------------------
// Launch
// ---------------------------------------------------------------------------
extern "C" void kernel_launch(void* const* d_in, const int* in_sizes, int n_in,
                              void* d_out, int out_size)
{
    const float* x   = (const float*)d_in[0];
    const float* ctx = (const float*)d_in[1];
    const float* w_q = (const float*)d_in[2];
    const float* b_q = (const float*)d_in[3];
    const float* w_k = (const float*)d_in[4];
    const float* b_k = (const float*)d_in[5];
    const float* w_v = (const float*)d_in[6];
    const float* b_v = (const float*)d_in[7];
    const float* w_o = (const float*)d_in[8];
    const float* b_o = (const float*)d_in[9];
    float* out = (float*)d_out;

    float *pq, *pk, *pv, *patt;
    cudaGetSymbolAddress((void**)&pq,   g_q);
    cudaGetSymbolAddress((void**)&pk,   g_k);
    cudaGetSymbolAddress((void**)&pv,   g_v);
    cudaGetSymbolAddress((void**)&patt, g_att);

    static int attn_smem_set = 0;
    if (!attn_smem_set) {
        cudaFuncSetAttribute(attn_mma, cudaFuncAttributeMaxDynamicSharedMemorySize,
                             ATTN_SMEM_FLOATS * sizeof(float));
        attn_smem_set = 1;
    }

    dim3 gb(DIM / 128, MROWS / 128);   // (8, 32)
    gemm3x<<<gb, 256>>>(x,   w_q, b_q, pq, MROWS, DIM, DIM);
    gemm3x<<<gb, 256>>>(ctx, w_k, b_k, pk, MROWS, DIM, DCTX);
    gemm3x<<<gb, 256>>>(ctx, w_v, b_v, pv, MROWS, DIM, DCTX);

    dim3 ga(B_BATCH * NH, LQ / 128);   // (32, 16)
    attn_mma<<<ga, 256, ATTN_SMEM_FLOATS * sizeof(float)>>>(pq, pk, pv, patt);

    gemm3x<<<gb, 256>>>(patt, w_o, b_o, out, MROWS, DIM, DIM);
}

// round 3
// speedup vs baseline: 2.1168x; 1.0000x over previous
#include <cuda_runtime.h>
#include <stdint.h>
#include <math.h>

// Problem constants (CrossAttention_7756710936941)
#define B_BATCH 2
#define LQ      2048
#define LK      2048
#define DIM     1024
#define DCTX    768
#define NH      16
#define HD      64
#define MROWS   (B_BATCH * LQ)

// Scratch (allocation-free: device globals)
__device__ float g_q[(size_t)MROWS * DIM];
__device__ float g_k[(size_t)MROWS * DIM];
__device__ float g_v[(size_t)MROWS * DIM];
__device__ float g_att[(size_t)MROWS * DIM];

// ---------------------------------------------------------------------------
// tf32 helpers
// ---------------------------------------------------------------------------
__device__ __forceinline__ uint32_t f2tf(float x) {
    uint32_t u;
    asm("cvt.rna.tf32.f32 %0, %1;" : "=r"(u) : "f"(x));
    return u;
}
__device__ __forceinline__ float f2tf_f(float x) { return __uint_as_float(f2tf(x)); }

// D += A(16x8) * B(8x8), tf32 inputs, f32 accum.
// A frag: a0=(g,tg) a1=(g+8,tg) a2=(g,tg+4) a3=(g+8,tg+4)   [row,colK]
// B frag: b0=(k=tg, n=g) b1=(k=tg+4, n=g)
// C frag: c0=(g,2tg) c1=(g,2tg+1) c2=(g+8,2tg) c3=(g+8,2tg+1)
__device__ __forceinline__ void mma_tf32(float c[4],
    uint32_t a0, uint32_t a1, uint32_t a2, uint32_t a3,
    uint32_t b0, uint32_t b1)
{
    asm volatile(
        "mma.sync.aligned.m16n8k8.row.col.f32.tf32.tf32.f32 "
        "{%0,%1,%2,%3},{%4,%5,%6,%7},{%8,%9},{%0,%1,%2,%3};"
        : "+f"(c[0]), "+f"(c[1]), "+f"(c[2]), "+f"(c[3])
        : "r"(a0), "r"(a1), "r"(a2), "r"(a3), "r"(b0), "r"(b1));
}

// ---------------------------------------------------------------------------
// 3xTF32 GEMM with bias: C[M,N] = A[M,K] @ Bw[K,N] + bias[N]  (~fp32 accuracy)
// 128x128 block, BK=16, 256 threads = 8 warps (4 m-warps x 2 n-warps),
// warp tile 32x64 = 2 m16-tiles x 8 n8-tiles.
// Smem row stride 136 words => fragment loads (8*tg+g banks) conflict-free.
// ---------------------------------------------------------------------------
#define GS 136

__global__ __launch_bounds__(256, 2) void gemm3x(
    const float* __restrict__ A, const float* __restrict__ Bw,
    const float* __restrict__ bias, float* __restrict__ C,
    int M, int N, int K)
{
    __shared__ float Ah[16][GS], Al[16][GS], Bh[16][GS], Bl[16][GS];

    const int t    = threadIdx.x;
    const int lane = t & 31;
    const int w    = t >> 5;
    const int g    = lane >> 2, tg = lane & 3;
    const int wm   = w >> 1,    wn = w & 1;
    const int m0   = blockIdx.y * 128, n0 = blockIdx.x * 128;

    float c[2][8][4];
#pragma unroll
    for (int i = 0; i < 2; i++)
#pragma unroll
        for (int j = 0; j < 8; j++)
#pragma unroll
            for (int e = 0; e < 4; e++) c[i][j][e] = 0.0f;

    const int ar0 = t >> 2,  ak0 = (t & 3) * 4;    // A: rows ar0, ar0+64
    const int br0 = t >> 5,  bn0 = (t & 31) * 4;   // B: k-rows br0, br0+8

    float4 ra0 = *(const float4*)(A + (size_t)(m0 + ar0) * K + ak0);
    float4 ra1 = *(const float4*)(A + (size_t)(m0 + ar0 + 64) * K + ak0);
    float4 rb0 = *(const float4*)(Bw + (size_t)br0 * N + n0 + bn0);
    float4 rb1 = *(const float4*)(Bw + (size_t)(br0 + 8) * N + n0 + bn0);

    for (int k0 = 0; k0 < K; k0 += 16) {
        __syncthreads();
        {
            float va[4] = {ra0.x, ra0.y, ra0.z, ra0.w};
#pragma unroll
            for (int e = 0; e < 4; e++) {
                float hi = f2tf_f(va[e]);
                Ah[ak0 + e][ar0] = hi;
                Al[ak0 + e][ar0] = f2tf_f(va[e] - hi);
            }
            float vb[4] = {ra1.x, ra1.y, ra1.z, ra1.w};
#pragma unroll
            for (int e = 0; e < 4; e++) {
                float hi = f2tf_f(vb[e]);
                Ah[ak0 + e][ar0 + 64] = hi;
                Al[ak0 + e][ar0 + 64] = f2tf_f(vb[e] - hi);
            }
            float4 h0, l0, h1, l1;
            h0.x = f2tf_f(rb0.x); l0.x = f2tf_f(rb0.x - h0.x);
            h0.y = f2tf_f(rb0.y); l0.y = f2tf_f(rb0.y - h0.y);
            h0.z = f2tf_f(rb0.z); l0.z = f2tf_f(rb0.z - h0.z);
            h0.w = f2tf_f(rb0.w); l0.w = f2tf_f(rb0.w - h0.w);
            h1.x = f2tf_f(rb1.x); l1.x = f2tf_f(rb1.x - h1.x);
            h1.y = f2tf_f(rb1.y); l1.y = f2tf_f(rb1.y - h1.y);
            h1.z = f2tf_f(rb1.z); l1.z = f2tf_f(rb1.z - h1.z);
            h1.w = f2tf_f(rb1.w); l1.w = f2tf_f(rb1.w - h1.w);
            *(float4*)&Bh[br0][bn0]     = h0;
            *(float4*)&Bl[br0][bn0]     = l0;
            *(float4*)&Bh[br0 + 8][bn0] = h1;
            *(float4*)&Bl[br0 + 8][bn0] = l1;
        }
        __syncthreads();

        if (k0 + 16 < K) {   // prefetch next tile while computing
            ra0 = *(const float4*)(A + (size_t)(m0 + ar0) * K + k0 + 16 + ak0);
            ra1 = *(const float4*)(A + (size_t)(m0 + ar0 + 64) * K + k0 + 16 + ak0);
            rb0 = *(const float4*)(Bw + (size_t)(k0 + 16 + br0) * N + n0 + bn0);
            rb1 = *(const float4*)(Bw + (size_t)(k0 + 24 + br0) * N + n0 + bn0);
        }

#pragma unroll
        for (int ks = 0; ks < 16; ks += 8) {
            uint32_t ah[2][4], alr[2][4];
#pragma unroll
            for (int mt = 0; mt < 2; mt++) {
                const int r = wm * 32 + mt * 16;
                ah[mt][0]  = __float_as_uint(Ah[ks + tg][r + g]);
                ah[mt][1]  = __float_as_uint(Ah[ks + tg][r + g + 8]);
                ah[mt][2]  = __float_as_uint(Ah[ks + tg + 4][r + g]);
                ah[mt][3]  = __float_as_uint(Ah[ks + tg + 4][r + g + 8]);
                alr[mt][0] = __float_as_uint(Al[ks + tg][r + g]);
                alr[mt][1] = __float_as_uint(Al[ks + tg][r + g + 8]);
                alr[mt][2] = __float_as_uint(Al[ks + tg + 4][r + g]);
                alr[mt][3] = __float_as_uint(Al[ks + tg + 4][r + g + 8]);
            }
#pragma unroll
            for (int nt = 0; nt < 8; nt++) {
                const int cb = wn * 64 + nt * 8 + g;
                uint32_t bh0 = __float_as_uint(Bh[ks + tg][cb]);
                uint32_t bh1 = __float_as_uint(Bh[ks + tg + 4][cb]);
                uint32_t bl0 = __float_as_uint(Bl[ks + tg][cb]);
                uint32_t bl1 = __float_as_uint(Bl[ks + tg + 4][cb]);
#pragma unroll
                for (int mt = 0; mt < 2; mt++) {
                    mma_tf32(c[mt][nt], ah[mt][0], ah[mt][1], ah[mt][2], ah[mt][3], bh0, bh1);
                    mma_tf32(c[mt][nt], ah[mt][0], ah[mt][1], ah[mt][2], ah[mt][3], bl0, bl1);
                    mma_tf32(c[mt][nt], alr[mt][0], alr[mt][1], alr[mt][2], alr[mt][3], bh0, bh1);
                }
            }
        }
    }

    // epilogue: bias + store (float2 per row-half)
#pragma unroll
    for (int mt = 0; mt < 2; mt++) {
        const int r = m0 + wm * 32 + mt * 16 + g;
#pragma unroll
        for (int nt = 0; nt < 8; nt++) {
            const int col = n0 + wn * 64 + nt * 8 + 2 * tg;
            const float b0v = bias[col], b1v = bias[col + 1];
            float2 s0 = make_float2(c[mt][nt][0] + b0v, c[mt][nt][1] + b1v);
            float2 s1 = make_float2(c[mt][nt][2] + b0v, c[mt][nt][3] + b1v);
            *(float2*)(C + (size_t)r * N + col)       = s0;
            *(float2*)(C + (size_t)(r + 8) * N + col) = s1;
        }
    }
}

// ---------------------------------------------------------------------------
// Flash cross-attention on tf32 tensor MMA.
// CTA = (b, h, 128-row q-tile), 8 warps; warp owns 16 q-rows (full softmax
// locality: no cross-warp reductions). Bc = 64 keys per step, HD = 64.
// S and PV via m16n8k8.tf32; online softmax in fp32; P round-trips through
// smem (tf32) — each warp reads back only its own rows => __syncwarp only.
// Smem strides 68/72 make every fragment load bank-conflict-free.
// ---------------------------------------------------------------------------
#define QSTR 68
#define VSTR 72
#define ATTN_SMEM_FLOATS (128 * QSTR + 64 * QSTR + 64 * VSTR + 128 * QSTR)

__global__ __launch_bounds__(256, 2) void attn_mma(
    const float* __restrict__ gq, const float* __restrict__ gk,
    const float* __restrict__ gv, float* __restrict__ gatt)
{
    extern __shared__ float smbuf[];
    float* Qs = smbuf;                    // [128][68]
    float* Ks = Qs + 128 * QSTR;          // [64][68]
    float* Vs = Ks + 64 * QSTR;           // [64][72]
    float* Ps = Vs + 64 * VSTR;           // [128][68]

    const int t    = threadIdx.x;
    const int lane = t & 31;
    const int w    = t >> 5;
    const int g    = lane >> 2, tg = lane & 3;
    const int m0   = w * 16;
    const int bh   = blockIdx.x;
    const int b    = bh >> 4, h = bh & 15;
    const int qt   = blockIdx.y;

    const float* qb  = gq + ((size_t)b * LQ + qt * 128) * DIM + h * HD;
    const float* kbp = gk + (size_t)b * LK * DIM + h * HD;
    const float* vbp = gv + (size_t)b * LK * DIM + h * HD;

    // Q tile: scale by 1/sqrt(HD), convert to tf32 once
#pragma unroll
    for (int j = 0; j < 8; j++) {
        int it = t + 256 * j;
        int r = it >> 4, d = (it & 15) * 4;
        float4 v = *(const float4*)(qb + (size_t)r * DIM + d);
        float4 o;
        o.x = f2tf_f(v.x * 0.125f); o.y = f2tf_f(v.y * 0.125f);
        o.z = f2tf_f(v.z * 0.125f); o.w = f2tf_f(v.w * 0.125f);
        *(float4*)&Qs[r * QSTR + d] = o;
    }

    float oacc[8][4];
#pragma unroll
    for (int dt = 0; dt < 8; dt++)
#pragma unroll
        for (int e = 0; e < 4; e++) oacc[dt][e] = 0.0f;
    float mrow0 = -1e30f, mrow1 = -1e30f, lrow0 = 0.0f, lrow1 = 0.0f;

    for (int kt = 0; kt < LK / 64; kt++) {
        __syncthreads();   // previous S/PV done with Ks/Vs
#pragma unroll
        for (int j = 0; j < 4; j++) {
            int it = t + 256 * j;
            int r = it >> 4, d = (it & 15) * 4;
            float4 kv = *(const float4*)(kbp + (size_t)(kt * 64 + r) * DIM + d);
            float4 vv = *(const float4*)(vbp + (size_t)(kt * 64 + r) * DIM + d);
            float4 ko, vo;
            ko.x = f2tf_f(kv.x); ko.y = f2tf_f(kv.y);
            ko.z = f2tf_f(kv.z); ko.w = f2tf_f(kv.w);
            vo.x = f2tf_f(vv.x); vo.y = f2tf_f(vv.y);
            vo.z = f2tf_f(vv.z); vo.w = f2tf_f(vv.w);
            *(float4*)&Ks[r * QSTR + d] = ko;
            *(float4*)&Vs[r * VSTR + d] = vo;
        }
        __syncthreads();

        // S = Q K^T  (warp: 16 x 64)
        float sc[8][4];
#pragma unroll
        for (int nt = 0; nt < 8; nt++)
#pragma unroll
            for (int e = 0; e < 4; e++) sc[nt][e] = 0.0f;

#pragma unroll
        for (int k0 = 0; k0 < 64; k0 += 8) {
            uint32_t a0 = __float_as_uint(Qs[(m0 + g) * QSTR + k0 + tg]);
            uint32_t a1 = __float_as_uint(Qs[(m0 + g + 8) * QSTR + k0 + tg]);
            uint32_t a2 = __float_as_uint(Qs[(m0 + g) * QSTR + k0 + tg + 4]);
            uint32_t a3 = __float_as_uint(Qs[(m0 + g + 8) * QSTR + k0 + tg + 4]);
#pragma unroll
            for (int nt = 0; nt < 8; nt++) {
                uint32_t b0 = __float_as_uint(Ks[(nt * 8 + g) * QSTR + k0 + tg]);
                uint32_t b1 = __float_as_uint(Ks[(nt * 8 + g) * QSTR + k0 + tg + 4]);
                mma_tf32(sc[nt], a0, a1, a2, a3, b0, b1);
            }
        }

        // online softmax (rows g and g+8; reduce across the tg quad)
        float mt0 = -1e30f, mt1 = -1e30f;
#pragma unroll
        for (int nt = 0; nt < 8; nt++) {
            mt0 = fmaxf(mt0, fmaxf(sc[nt][0], sc[nt][1]));
            mt1 = fmaxf(mt1, fmaxf(sc[nt][2], sc[nt][3]));
        }
        mt0 = fmaxf(mt0, __shfl_xor_sync(0xffffffffu, mt0, 1));
        mt0 = fmaxf(mt0, __shfl_xor_sync(0xffffffffu, mt0, 2));
        mt1 = fmaxf(mt1, __shfl_xor_sync(0xffffffffu, mt1, 1));
        mt1 = fmaxf(mt1, __shfl_xor_sync(0xffffffffu, mt1, 2));

        float mn0 = fmaxf(mrow0, mt0), mn1 = fmaxf(mrow1, mt1);
        float al0 = __expf(mrow0 - mn0), al1 = __expf(mrow1 - mn1);
        mrow0 = mn0; mrow1 = mn1;

        float ls0 = 0.0f, ls1 = 0.0f;
#pragma unroll
        for (int nt = 0; nt < 8; nt++) {
            float p0 = __expf(sc[nt][0] - mn0);
            float p1 = __expf(sc[nt][1] - mn0);
            float p2 = __expf(sc[nt][2] - mn1);
            float p3 = __expf(sc[nt][3] - mn1);
            ls0 += p0 + p1; ls1 += p2 + p3;
            float2 w0 = make_float2(f2tf_f(p0), f2tf_f(p1));
            float2 w1 = make_float2(f2tf_f(p2), f2tf_f(p3));
            *(float2*)&Ps[(m0 + g) * QSTR + nt * 8 + 2 * tg]     = w0;
            *(float2*)&Ps[(m0 + g + 8) * QSTR + nt * 8 + 2 * tg] = w1;
        }
        ls0 += __shfl_xor_sync(0xffffffffu, ls0, 1);
        ls0 += __shfl_xor_sync(0xffffffffu, ls0, 2);
        ls1 += __shfl_xor_sync(0xffffffffu, ls1, 1);
        ls1 += __shfl_xor_sync(0xffffffffu, ls1, 2);
        lrow0 = lrow0 * al0 + ls0;
        lrow1 = lrow1 * al1 + ls1;
#pragma unroll
        for (int dt = 0; dt < 8; dt++) {
            oacc[dt][0] *= al0; oacc[dt][1] *= al0;
            oacc[dt][2] *= al1; oacc[dt][3] *= al1;
        }
        __syncwarp();   // P stores visible warp-wide (warp reads only its own rows)

        // O += P V  (warp: 16 x 64)
#pragma unroll
        for (int kk = 0; kk < 64; kk += 8) {
            uint32_t a0 = __float_as_uint(Ps[(m0 + g) * QSTR + kk + tg]);
            uint32_t a1 = __float_as_uint(Ps[(m0 + g + 8) * QSTR + kk + tg]);
            uint32_t a2 = __float_as_uint(Ps[(m0 + g) * QSTR + kk + tg + 4]);
            uint32_t a3 = __float_as_uint(Ps[(m0 + g + 8) * QSTR + kk + tg + 4]);
#pragma unroll
            for (int dt = 0; dt < 8; dt++) {
                uint32_t b0 = __float_as_uint(Vs[(kk + tg) * VSTR + dt * 8 + g]);
                uint32_t b1 = __float_as_uint(Vs[(kk + tg + 4) * VSTR + dt * 8 + g]);
                mma_tf32(oacc[dt], a0, a1, a2, a3, b0, b1);
            }
        }
    }

    const float i0 = 1.0f / lrow0, i1 = 1.0f / lrow1;
    float* ob = gatt + ((size_t)b * LQ + qt * 128) * DIM + h * HD;
#pragma unroll
    for (int dt = 0; dt < 8; dt++) {
        const int col = dt * 8 + 2 * tg;
        float2 s0 = make_float2(oacc[dt][0] * i0, oacc[dt][1] * i0);
        float2 s1 = make_float2(oacc[dt][2] * i1, oacc[dt][3] * i1);
        *(float2*)(ob + (size_t)(m0 + g) * DIM + col)     = s0;
        *(float2*)(ob + (size_t)(m0 + g + 8) * DIM + col) = s1;
    }
}

// ---------------------------------------------------------------------------
// Launch
// ---------------------------------------------------------------------------
extern "C" void kernel_launch(void* const* d_in, const int* in_sizes, int n_in,
                              void* d_out, int out_size)
{
    const float* x   = (const float*)d_in[0];
    const float* ctx = (const float*)d_in[1];
    const float* w_q = (const float*)d_in[2];
    const float* b_q = (const float*)d_in[3];
    const float* w_k = (const float*)d_in[4];
    const float* b_k = (const float*)d_in[5];
    const float* w_v = (const float*)d_in[6];
    const float* b_v = (const float*)d_in[7];
    const float* w_o = (const float*)d_in[8];
    const float* b_o = (const float*)d_in[9];
    float* out = (float*)d_out;

    float *pq, *pk, *pv, *patt;
    cudaGetSymbolAddress((void**)&pq,   g_q);
    cudaGetSymbolAddress((void**)&pk,   g_k);
    cudaGetSymbolAddress((void**)&pv,   g_v);
    cudaGetSymbolAddress((void**)&patt, g_att);

    static int attn_smem_set = 0;
    if (!attn_smem_set) {
        cudaFuncSetAttribute(attn_mma, cudaFuncAttributeMaxDynamicSharedMemorySize,
                             ATTN_SMEM_FLOATS * sizeof(float));
        attn_smem_set = 1;
    }

    dim3 gb(DIM / 128, MROWS / 128);   // (8, 32)
    gemm3x<<<gb, 256>>>(x,   w_q, b_q, pq, MROWS, DIM, DIM);
    gemm3x<<<gb, 256>>>(ctx, w_k, b_k, pk, MROWS, DIM, DCTX);
    gemm3x<<<gb, 256>>>(ctx, w_v, b_v, pv, MROWS, DIM, DCTX);

    dim3 ga(B_BATCH * NH, LQ / 128);   // (32, 16)
    attn_mma<<<ga, 256, ATTN_SMEM_FLOATS * sizeof(float)>>>(pq, pk, pv, patt);

    gemm3x<<<gb, 256>>>(patt, w_o, b_o, out, MROWS, DIM, DIM);
}

// round 4
// speedup vs baseline: 2.9090x; 1.3742x over previous
#include <cuda_runtime.h>
#include <cuda_bf16.h>
#include <stdint.h>
#include <math.h>

// Problem constants (CrossAttention_7756710936941)
#define B_BATCH 2
#define LQ      2048
#define LK      2048
#define DIM     1024
#define DCTX    768
#define NH      16
#define HD      64
#define MROWS   (B_BATCH * LQ)

// Scratch (allocation-free: device globals)
__device__ float g_q[(size_t)MROWS * DIM];
__device__ float g_k[(size_t)MROWS * DIM];
__device__ float g_v[(size_t)MROWS * DIM];
__device__ float g_att[(size_t)MROWS * DIM];

// ---------------------------------------------------------------------------
// helpers
// ---------------------------------------------------------------------------
__device__ __forceinline__ uint32_t f2tf(float x) {
    uint32_t u;
    asm("cvt.rna.tf32.f32 %0, %1;" : "=r"(u) : "f"(x));
    return u;
}
__device__ __forceinline__ float f2tf_f(float x) { return __uint_as_float(f2tf(x)); }

// D += A(16x8) * B(8x8), tf32, f32 accum. Frags per PTX spec (g=lane>>2, tg=lane&3):
// A: a0=(g,tg) a1=(g+8,tg) a2=(g,tg+4) a3=(g+8,tg+4); B: b0=(k=tg,n=g) b1=(k=tg+4,n=g)
// C: c0=(g,2tg) c1=(g,2tg+1) c2=(g+8,2tg) c3=(g+8,2tg+1)
__device__ __forceinline__ void mma_tf32(float c[4],
    uint32_t a0, uint32_t a1, uint32_t a2, uint32_t a3, uint32_t b0, uint32_t b1)
{
    asm volatile(
        "mma.sync.aligned.m16n8k8.row.col.f32.tf32.tf32.f32 "
        "{%0,%1,%2,%3},{%4,%5,%6,%7},{%8,%9},{%0,%1,%2,%3};"
        : "+f"(c[0]), "+f"(c[1]), "+f"(c[2]), "+f"(c[3])
        : "r"(a0), "r"(a1), "r"(a2), "r"(a3), "r"(b0), "r"(b1));
}

// D += A(16x16) * B(16x8), bf16, f32 accum.
// A: a0=(g, k 2tg..2tg+1) a1=(g+8, same) a2=(g, k 2tg+8..9) a3=(g+8, same)
// B: b0=(n g, k 2tg..2tg+1) b1=(n g, k 2tg+8..9)   (even k in low half)
__device__ __forceinline__ void mma_bf16(float c[4],
    uint32_t a0, uint32_t a1, uint32_t a2, uint32_t a3, uint32_t b0, uint32_t b1)
{
    asm volatile(
        "mma.sync.aligned.m16n8k16.row.col.f32.bf16.bf16.f32 "
        "{%0,%1,%2,%3},{%4,%5,%6,%7},{%8,%9},{%0,%1,%2,%3};"
        : "+f"(c[0]), "+f"(c[1]), "+f"(c[2]), "+f"(c[3])
        : "r"(a0), "r"(a1), "r"(a2), "r"(a3), "r"(b0), "r"(b1));
}

__device__ __forceinline__ uint32_t pack_bf16_hi(float x0, float x1, float& r0, float& r1) {
    __nv_bfloat162 h = __floats2bfloat162_rn(x0, x1);  // x0 -> low half (even k)
    r0 = x0 - __bfloat162float(h.x);
    r1 = x1 - __bfloat162float(h.y);
    uint32_t u; *(__nv_bfloat162*)&u = h; return u;
}
__device__ __forceinline__ uint32_t pack_bf16(float x0, float x1) {
    __nv_bfloat162 h = __floats2bfloat162_rn(x0, x1);
    uint32_t u; *(__nv_bfloat162*)&u = h; return u;
}

// ---------------------------------------------------------------------------
// bf16 3-term GEMM with bias: C = A @ Bw + bias   (~fp32 accuracy)
// 128x128 block, BK=16, 8 warps (4m x 2n), warp tile 32x64.
// A smem [m][kword] stride 12 (bf16x2 words), B smem transposed [n][kword]
// stride 12 with per-row XOR group swizzle (kills transpose-store conflicts).
// ---------------------------------------------------------------------------
#define GKW 12

__global__ __launch_bounds__(256, 2) void gemm_bf16_3x(
    const float* __restrict__ A, const float* __restrict__ Bw,
    const float* __restrict__ bias, float* __restrict__ C,
    int M, int N, int K)
{
    __shared__ uint32_t Ah[128 * GKW], Al[128 * GKW];
    __shared__ uint32_t Bh[128 * GKW], Bl[128 * GKW];

    const int t    = threadIdx.x;
    const int lane = t & 31;
    const int w    = t >> 5;
    const int g    = lane >> 2, tg = lane & 3;
    const int wm   = w >> 1,    wn = w & 1;
    const int m0   = blockIdx.y * 128, n0 = blockIdx.x * 128;

    float c[2][8][4];
#pragma unroll
    for (int i = 0; i < 2; i++)
#pragma unroll
        for (int j = 0; j < 8; j++)
#pragma unroll
            for (int e = 0; e < 4; e++) c[i][j][e] = 0.0f;

    const int ar  = t >> 1;          // A row 0..127
    const int akh = (t & 1) * 8;     // A k offset (8 floats)
    const int bn  = t & 127;         // B n col 0..127
    const int bkh = (t >> 7) * 8;    // B k offset (8 floats)
    // swizzle parity for row bn: phys group = logical group ^ sB
    const int sB  = ((bn >> 3) ^ (bn >> 4)) & 1;

    float apf[8], bpf[8];
    {
        float4 v0 = *(const float4*)(A + (size_t)(m0 + ar) * K + akh);
        float4 v1 = *(const float4*)(A + (size_t)(m0 + ar) * K + akh + 4);
        apf[0]=v0.x; apf[1]=v0.y; apf[2]=v0.z; apf[3]=v0.w;
        apf[4]=v1.x; apf[5]=v1.y; apf[6]=v1.z; apf[7]=v1.w;
#pragma unroll
        for (int j = 0; j < 8; j++)
            bpf[j] = Bw[(size_t)(bkh + j) * N + n0 + bn];
    }

    for (int k0 = 0; k0 < K; k0 += 16) {
        __syncthreads();
        {   // A: pack hi/lo, store [m][kword]
            uint32_t hw[4], lw[4];
#pragma unroll
            for (int p = 0; p < 4; p++) {
                float r0, r1;
                hw[p] = pack_bf16_hi(apf[2*p], apf[2*p+1], r0, r1);
                lw[p] = pack_bf16(r0, r1);
            }
            *(uint4*)&Ah[ar * GKW + (t & 1) * 4] = make_uint4(hw[0], hw[1], hw[2], hw[3]);
            *(uint4*)&Al[ar * GKW + (t & 1) * 4] = make_uint4(lw[0], lw[1], lw[2], lw[3]);
        }
        {   // B: pack hi/lo, store transposed [n][kword] with group swizzle
            uint32_t hw[4], lw[4];
#pragma unroll
            for (int p = 0; p < 4; p++) {
                float r0, r1;
                hw[p] = pack_bf16_hi(bpf[2*p], bpf[2*p+1], r0, r1);
                lw[p] = pack_bf16(r0, r1);
            }
            const int grp = ((t >> 7) ^ sB) * 4;   // phys group
            *(uint4*)&Bh[bn * GKW + grp] = make_uint4(hw[0], hw[1], hw[2], hw[3]);
            *(uint4*)&Bl[bn * GKW + grp] = make_uint4(lw[0], lw[1], lw[2], lw[3]);
        }
        __syncthreads();

        if (k0 + 16 < K) {
            float4 v0 = *(const float4*)(A + (size_t)(m0 + ar) * K + k0 + 16 + akh);
            float4 v1 = *(const float4*)(A + (size_t)(m0 + ar) * K + k0 + 16 + akh + 4);
            apf[0]=v0.x; apf[1]=v0.y; apf[2]=v0.z; apf[3]=v0.w;
            apf[4]=v1.x; apf[5]=v1.y; apf[6]=v1.z; apf[7]=v1.w;
#pragma unroll
            for (int j = 0; j < 8; j++)
                bpf[j] = Bw[(size_t)(k0 + 16 + bkh + j) * N + n0 + bn];
        }

        uint32_t ah[2][4], al[2][4];
#pragma unroll
        for (int mt = 0; mt < 2; mt++) {
            const int rA = wm * 32 + mt * 16;
            ah[mt][0] = Ah[(rA + g) * GKW + tg];
            ah[mt][1] = Ah[(rA + g + 8) * GKW + tg];
            ah[mt][2] = Ah[(rA + g) * GKW + tg + 4];
            ah[mt][3] = Ah[(rA + g + 8) * GKW + tg + 4];
            al[mt][0] = Al[(rA + g) * GKW + tg];
            al[mt][1] = Al[(rA + g + 8) * GKW + tg];
            al[mt][2] = Al[(rA + g) * GKW + tg + 4];
            al[mt][3] = Al[(rA + g + 8) * GKW + tg + 4];
        }
#pragma unroll
        for (int nt = 0; nt < 8; nt++) {
            const int nB = wn * 64 + nt * 8 + g;
            const int s  = (nt & 1) ^ ((nt >> 1) & 1);   // == swizzle parity of nB
            uint32_t bh0 = Bh[nB * GKW + s * 4 + tg];
            uint32_t bh1 = Bh[nB * GKW + (1 - s) * 4 + tg];
            uint32_t bl0 = Bl[nB * GKW + s * 4 + tg];
            uint32_t bl1 = Bl[nB * GKW + (1 - s) * 4 + tg];
#pragma unroll
            for (int mt = 0; mt < 2; mt++) {
                mma_bf16(c[mt][nt], ah[mt][0], ah[mt][1], ah[mt][2], ah[mt][3], bh0, bh1);
                mma_bf16(c[mt][nt], ah[mt][0], ah[mt][1], ah[mt][2], ah[mt][3], bl0, bl1);
                mma_bf16(c[mt][nt], al[mt][0], al[mt][1], al[mt][2], al[mt][3], bh0, bh1);
            }
        }
    }

#pragma unroll
    for (int mt = 0; mt < 2; mt++) {
        const int r = m0 + wm * 32 + mt * 16 + g;
#pragma unroll
        for (int nt = 0; nt < 8; nt++) {
            const int col = n0 + wn * 64 + nt * 8 + 2 * tg;
            const float b0v = bias[col], b1v = bias[col + 1];
            float2 s0 = make_float2(c[mt][nt][0] + b0v, c[mt][nt][1] + b1v);
            float2 s1 = make_float2(c[mt][nt][2] + b0v, c[mt][nt][3] + b1v);
            *(float2*)(C + (size_t)r * N + col)       = s0;
            *(float2*)(C + (size_t)(r + 8) * N + col) = s1;
        }
    }
}

// ---------------------------------------------------------------------------
// Flash cross-attention, tf32 MMA, cp.async double-buffered K/V,
// register shuffle-transpose for P (no P smem).
// CTA = (b,h,128-q-rows), 8 warps x 16 rows, Bc=64.
// ---------------------------------------------------------------------------
#define KSTR 68
#define VSTR 72
#define SM_Q  (128 * KSTR)
#define SM_K  (64 * KSTR)
#define SM_V  (64 * VSTR)
#define ATTN_SMEM_FLOATS (SM_Q + 2 * SM_K + 2 * SM_V)

__device__ __forceinline__ void cp_async16(uint32_t dst, const void* src) {
    asm volatile("cp.async.cg.shared.global [%0], [%1], 16;" :: "r"(dst), "l"(src));
}

__global__ __launch_bounds__(256, 2) void attn_mma2(
    const float* __restrict__ gq, const float* __restrict__ gk,
    const float* __restrict__ gv, float* __restrict__ gatt)
{
    extern __shared__ float sm[];
    float* Qs = sm;
    float* Kd = Qs + SM_Q;
    float* Vd = Kd + 2 * SM_K;
    const uint32_t smb   = (uint32_t)__cvta_generic_to_shared(sm);
    const uint32_t kdstB = smb + SM_Q * 4;
    const uint32_t vdstB = smb + (SM_Q + 2 * SM_K) * 4;

    const int t    = threadIdx.x;
    const int lane = t & 31;
    const int w    = t >> 5;
    const int g    = lane >> 2, tg = lane & 3;
    const int m0   = w * 16;
    const int bh   = blockIdx.x;
    const int b    = bh >> 4, h = bh & 15;
    const int qt   = blockIdx.y;

    const float* qb  = gq + ((size_t)b * LQ + qt * 128) * DIM + h * HD;
    const float* kbp = gk + (size_t)b * LK * DIM + h * HD;
    const float* vbp = gv + (size_t)b * LK * DIM + h * HD;

    // Q tile: scale, cvt tf32 once
#pragma unroll
    for (int j = 0; j < 8; j++) {
        int it = t + 256 * j;
        int r = it >> 4, d = (it & 15) * 4;
        float4 v = *(const float4*)(qb + (size_t)r * DIM + d);
        float4 o;
        o.x = f2tf_f(v.x * 0.125f); o.y = f2tf_f(v.y * 0.125f);
        o.z = f2tf_f(v.z * 0.125f); o.w = f2tf_f(v.w * 0.125f);
        *(float4*)&Qs[r * KSTR + d] = o;
    }

    // prologue: async-load tile 0 into buf 0
    {
#pragma unroll
        for (int j = 0; j < 4; j++) {
            int it = t + 256 * j;
            int r = it >> 4, c4 = (it & 15) * 4;
            cp_async16(kdstB + (uint32_t)(r * KSTR + c4) * 4, kbp + (size_t)r * DIM + c4);
            cp_async16(vdstB + (uint32_t)(r * VSTR + c4) * 4, vbp + (size_t)r * DIM + c4);
        }
        asm volatile("cp.async.commit_group;" ::: "memory");
    }

    float oacc[8][4];
#pragma unroll
    for (int dt = 0; dt < 8; dt++)
#pragma unroll
        for (int e = 0; e < 4; e++) oacc[dt][e] = 0.0f;
    float mrow0 = -1e30f, mrow1 = -1e30f, lrow0 = 0.0f, lrow1 = 0.0f;

    for (int kt = 0; kt < LK / 64; kt++) {
        asm volatile("cp.async.wait_group 0;" ::: "memory");
        __syncthreads();   // tile kt resident everywhere; prev compute done

        if (kt + 1 < LK / 64) {   // prefetch kt+1 into other buffer
            const uint32_t kd = kdstB + (uint32_t)(((kt + 1) & 1) * SM_K) * 4;
            const uint32_t vd = vdstB + (uint32_t)(((kt + 1) & 1) * SM_V) * 4;
            const float* kp = kbp + (size_t)(kt + 1) * 64 * DIM;
            const float* vp = vbp + (size_t)(kt + 1) * 64 * DIM;
#pragma unroll
            for (int j = 0; j < 4; j++) {
                int it = t + 256 * j;
                int r = it >> 4, c4 = (it & 15) * 4;
                cp_async16(kd + (uint32_t)(r * KSTR + c4) * 4, kp + (size_t)r * DIM + c4);
                cp_async16(vd + (uint32_t)(r * VSTR + c4) * 4, vp + (size_t)r * DIM + c4);
            }
            asm volatile("cp.async.commit_group;" ::: "memory");
        }

        const float* Ks = Kd + (kt & 1) * SM_K;
        const float* Vs = Vd + (kt & 1) * SM_V;

        // S = Q K^T
        float sc[8][4];
#pragma unroll
        for (int nt = 0; nt < 8; nt++)
#pragma unroll
            for (int e = 0; e < 4; e++) sc[nt][e] = 0.0f;
#pragma unroll
        for (int d0 = 0; d0 < 64; d0 += 8) {
            uint32_t a0 = __float_as_uint(Qs[(m0 + g) * KSTR + d0 + tg]);
            uint32_t a1 = __float_as_uint(Qs[(m0 + g + 8) * KSTR + d0 + tg]);
            uint32_t a2 = __float_as_uint(Qs[(m0 + g) * KSTR + d0 + tg + 4]);
            uint32_t a3 = __float_as_uint(Qs[(m0 + g + 8) * KSTR + d0 + tg + 4]);
#pragma unroll
            for (int nt = 0; nt < 8; nt++) {
                uint32_t b0 = f2tf(Ks[(nt * 8 + g) * KSTR + d0 + tg]);
                uint32_t b1 = f2tf(Ks[(nt * 8 + g) * KSTR + d0 + tg + 4]);
                mma_tf32(sc[nt], a0, a1, a2, a3, b0, b1);
            }
        }

        // online softmax (rows g, g+8; reduce over quad lanes)
        float mt0 = -1e30f, mt1 = -1e30f;
#pragma unroll
        for (int nt = 0; nt < 8; nt++) {
            mt0 = fmaxf(mt0, fmaxf(sc[nt][0], sc[nt][1]));
            mt1 = fmaxf(mt1, fmaxf(sc[nt][2], sc[nt][3]));
        }
        mt0 = fmaxf(mt0, __shfl_xor_sync(0xffffffffu, mt0, 1));
        mt0 = fmaxf(mt0, __shfl_xor_sync(0xffffffffu, mt0, 2));
        mt1 = fmaxf(mt1, __shfl_xor_sync(0xffffffffu, mt1, 1));
        mt1 = fmaxf(mt1, __shfl_xor_sync(0xffffffffu, mt1, 2));

        float mn0 = fmaxf(mrow0, mt0), mn1 = fmaxf(mrow1, mt1);
        float al0 = __expf(mrow0 - mn0), al1 = __expf(mrow1 - mn1);
        mrow0 = mn0; mrow1 = mn1;

        float ls0 = 0.0f, ls1 = 0.0f;
#pragma unroll
        for (int nt = 0; nt < 8; nt++) {
            sc[nt][0] = __expf(sc[nt][0] - mn0);
            sc[nt][1] = __expf(sc[nt][1] - mn0);
            sc[nt][2] = __expf(sc[nt][2] - mn1);
            sc[nt][3] = __expf(sc[nt][3] - mn1);
            ls0 += sc[nt][0] + sc[nt][1];
            ls1 += sc[nt][2] + sc[nt][3];
        }
        ls0 += __shfl_xor_sync(0xffffffffu, ls0, 1);
        ls0 += __shfl_xor_sync(0xffffffffu, ls0, 2);
        ls1 += __shfl_xor_sync(0xffffffffu, ls1, 1);
        ls1 += __shfl_xor_sync(0xffffffffu, ls1, 2);
        lrow0 = lrow0 * al0 + ls0;
        lrow1 = lrow1 * al1 + ls1;
#pragma unroll
        for (int dt = 0; dt < 8; dt++) {
            oacc[dt][0] *= al0; oacc[dt][1] *= al0;
            oacc[dt][2] *= al1; oacc[dt][3] *= al1;
        }

        // O += P V : P C-frag -> A-frag via quad shuffles (no smem round trip)
        const int src0 = 4 * g + (tg >> 1);
        const int src2 = src0 + 2;
        const bool odd = (tg & 1) != 0;
#pragma unroll
        for (int ntk = 0; ntk < 8; ntk++) {
            const int kk = ntk * 8;
            float p0 = __uint_as_float(f2tf(sc[ntk][0]));
            float p1 = __uint_as_float(f2tf(sc[ntk][1]));
            float p2 = __uint_as_float(f2tf(sc[ntk][2]));
            float p3 = __uint_as_float(f2tf(sc[ntk][3]));
            float e0 = __shfl_sync(0xffffffffu, p0, src0, 32);
            float e1 = __shfl_sync(0xffffffffu, p1, src0, 32);
            float f0 = __shfl_sync(0xffffffffu, p0, src2, 32);
            float f1 = __shfl_sync(0xffffffffu, p1, src2, 32);
            float q0 = __shfl_sync(0xffffffffu, p2, src0, 32);
            float q1 = __shfl_sync(0xffffffffu, p3, src0, 32);
            float h0 = __shfl_sync(0xffffffffu, p2, src2, 32);
            float h1 = __shfl_sync(0xffffffffu, p3, src2, 32);
            uint32_t a0 = __float_as_uint(odd ? e1 : e0);
            uint32_t a1 = __float_as_uint(odd ? q1 : q0);
            uint32_t a2 = __float_as_uint(odd ? f1 : f0);
            uint32_t a3 = __float_as_uint(odd ? h1 : h0);
#pragma unroll
            for (int dt = 0; dt < 8; dt++) {
                uint32_t b0 = f2tf(Vs[(kk + tg) * VSTR + dt * 8 + g]);
                uint32_t b1 = f2tf(Vs[(kk + tg + 4) * VSTR + dt * 8 + g]);
                mma_tf32(oacc[dt], a0, a1, a2, a3, b0, b1);
            }
        }
    }

    const float i0 = 1.0f / lrow0, i1 = 1.0f / lrow1;
    float* ob = gatt + ((size_t)b * LQ + qt * 128) * DIM + h * HD;
#pragma unroll
    for (int dt = 0; dt < 8; dt++) {
        const int col = dt * 8 + 2 * tg;
        float2 s0 = make_float2(oacc[dt][0] * i0, oacc[dt][1] * i0);
        float2 s1 = make_float2(oacc[dt][2] * i1, oacc[dt][3] * i1);
        *(float2*)(ob + (size_t)(m0 + g) * DIM + col)     = s0;
        *(float2*)(ob + (size_t)(m0 + g + 8) * DIM + col) = s1;
    }
}

// ---------------------------------------------------------------------------
// Launch
// ---------------------------------------------------------------------------
extern "C" void kernel_launch(void* const* d_in, const int* in_sizes, int n_in,
                              void* d_out, int out_size)
{
    const float* x   = (const float*)d_in[0];
    const float* ctx = (const float*)d_in[1];
    const float* w_q = (const float*)d_in[2];
    const float* b_q = (const float*)d_in[3];
    const float* w_k = (const float*)d_in[4];
    const float* b_k = (const float*)d_in[5];
    const float* w_v = (const float*)d_in[6];
    const float* b_v = (const float*)d_in[7];
    const float* w_o = (const float*)d_in[8];
    const float* b_o = (const float*)d_in[9];
    float* out = (float*)d_out;

    float *pq, *pk, *pv, *patt;
    cudaGetSymbolAddress((void**)&pq,   g_q);
    cudaGetSymbolAddress((void**)&pk,   g_k);
    cudaGetSymbolAddress((void**)&pv,   g_v);
    cudaGetSymbolAddress((void**)&patt, g_att);

    static int attn_smem_set = 0;
    if (!attn_smem_set) {
        cudaFuncSetAttribute(attn_mma2, cudaFuncAttributeMaxDynamicSharedMemorySize,
                             ATTN_SMEM_FLOATS * sizeof(float));
        attn_smem_set = 1;
    }

    dim3 gb(DIM / 128, MROWS / 128);   // (8, 32)
    gemm_bf16_3x<<<gb, 256>>>(x,   w_q, b_q, pq, MROWS, DIM, DIM);
    gemm_bf16_3x<<<gb, 256>>>(ctx, w_k, b_k, pk, MROWS, DIM, DCTX);
    gemm_bf16_3x<<<gb, 256>>>(ctx, w_v, b_v, pv, MROWS, DIM, DCTX);

    dim3 ga(B_BATCH * NH, LQ / 128);   // (32, 16)
    attn_mma2<<<ga, 256, ATTN_SMEM_FLOATS * sizeof(float)>>>(pq, pk, pv, patt);

    gemm_bf16_3x<<<gb, 256>>>(patt, w_o, b_o, out, MROWS, DIM, DIM);
}